// round 10
// baseline (speedup 1.0000x reference)
#include <cuda_runtime.h>

static constexpr int CHW     = 3 * 128 * 128;    // 49152 floats
static constexpr int CHW4    = CHW / 4;          // 12288 float4
static constexpr int S       = 16;
static constexpr int N       = 64;
static constexpr int SG      = 8;                // 8 groups x 2 samples
static constexpr int CHUNKS  = 2;                // halves of CHW
static constexpr int CHUNK4  = CHW4 / CHUNKS;    // 6144 float4
static constexpr int GRID    = N * SG * CHUNKS;  // 1024 blocks

// one partial per (n, s, chunk): 64*16*2 = 2048
__device__ float        g_partial[N * S * CHUNKS];
__device__ unsigned int g_count = 0;

__global__ __launch_bounds__(512)
void fused_min_dist_kernel(const float* __restrict__ inputs,
                           const float* __restrict__ samples,
                           float* __restrict__ out) {
    const int blk = blockIdx.x;              // 0..1023
    const int n   = blk >> 4;
    const int sg  = (blk >> 1) & 7;          // sample pair: 2*sg, 2*sg+1
    const int c   = blk & 1;                 // half of CHW

    const size_t off = (size_t)c * CHUNK4;
    const float4* __restrict__ in4 =
        reinterpret_cast<const float4*>(inputs + (size_t)n * CHW) + off;
    const float4* __restrict__ s0 =
        reinterpret_cast<const float4*>(samples + ((size_t)n * S + 2 * sg + 0) * CHW) + off;
    const float4* __restrict__ s1 =
        reinterpret_cast<const float4*>(samples + ((size_t)n * S + 2 * sg + 1) * CHW) + off;

    // Long-stream shape (R1-proven): 12 iters/thread, 3 plain float4 loads/iter,
    // moderate unroll -> pipelined steady state, bounded MLP_p1.
    float a0 = 0.0f, a1 = 0.0f;
    #pragma unroll 4
    for (int i = threadIdx.x; i < CHUNK4; i += 512) {   // 12 iters
        float4 a  = in4[i];
        float4 b0 = s0[i];
        float4 b1 = s1[i];

        float dx, dy, dz, dw;
        dx = b0.x - a.x; dy = b0.y - a.y; dz = b0.z - a.z; dw = b0.w - a.w;
        a0 = fmaf(dx, dx, a0); a0 = fmaf(dy, dy, a0);
        a0 = fmaf(dz, dz, a0); a0 = fmaf(dw, dw, a0);
        dx = b1.x - a.x; dy = b1.y - a.y; dz = b1.z - a.z; dw = b1.w - a.w;
        a1 = fmaf(dx, dx, a1); a1 = fmaf(dy, dy, a1);
        a1 = fmaf(dz, dz, a1); a1 = fmaf(dw, dw, a1);
    }

    // Warp-level sums.
    #pragma unroll
    for (int o = 16; o > 0; o >>= 1) {
        a0 += __shfl_down_sync(0xffffffffu, a0, o);
        a1 += __shfl_down_sync(0xffffffffu, a1, o);
    }
    __shared__ float swarp[16][2];
    const int l = threadIdx.x & 31;
    const int w = threadIdx.x >> 5;
    if (l == 0) {
        swarp[w][0] = a0;
        swarp[w][1] = a1;
    }
    __syncthreads();
    // 2 threads each sum their sample's 16 warp partials (serial, deterministic).
    if (threadIdx.x < 2) {
        const int j = threadIdx.x;
        float v = 0.0f;
        #pragma unroll
        for (int ww = 0; ww < 16; ww++)
            v += swarp[ww][j];
        g_partial[((size_t)n * S + 2 * sg + j) * CHUNKS + c] = v;
    }

    // ---- last-block-finishes final reduction ----
    __shared__ bool is_last;
    __threadfence();
    __syncthreads();
    if (threadIdx.x == 0) {
        unsigned int prev = atomicInc(&g_count, GRID - 1);   // self-resetting
        is_last = (prev == GRID - 1);
    }
    __syncthreads();

    if (is_last) {
        __shared__ float sh[N * S];
        // 1024 (n,s) pairs / 512 threads = 2 each; 2 chunk partials per pair.
        #pragma unroll
        for (int r = 0; r < 2; r++) {
            const int p = threadIdx.x + r * 512;
            float sum = 0.0f;
            #pragma unroll
            for (int k = 0; k < CHUNKS; k++)
                sum += __ldcg(&g_partial[(size_t)p * CHUNKS + k]);  // L1-bypass, coherent
            sh[p] = sum;
        }
        __syncthreads();

        __shared__ float mins[N];
        if (threadIdx.x < N) {
            const int nn = threadIdx.x;
            float m = sh[nn * S];
            #pragma unroll
            for (int ss = 1; ss < S; ss++)
                m = fminf(m, sh[nn * S + ss]);
            mins[nn] = m;
        }
        __syncthreads();

        if (threadIdx.x == 0) {
            float total = 0.0f;
            #pragma unroll
            for (int nn = 0; nn < N; nn++)
                total += mins[nn];          // fixed order -> deterministic
            out[0] = total;
        }
    }
}

extern "C" void kernel_launch(void* const* d_in, const int* in_sizes, int n_in,
                              void* d_out, int out_size) {
    const float* inputs  = (const float*)d_in[0];   // [64,3,128,128]
    const float* samples = (const float*)d_in[1];   // [64,16,3,128,128]
    float* out = (float*)d_out;

    fused_min_dist_kernel<<<GRID, 512>>>(inputs, samples, out);
}

// round 11
// speedup vs baseline: 1.1158x; 1.1158x over previous
#include <cuda_runtime.h>

static constexpr int CHW   = 3 * 128 * 128;   // 49152
static constexpr int CHW4  = CHW / 4;         // 12288 float4
static constexpr int S     = 16;
static constexpr int N     = 64;
static constexpr int GRID  = N * S;           // 1024 blocks, one (n,s) each

// min over s tracked as max of ~bits(dist) (dist >= 0): zero-init is identity,
// atomicMax is commutative -> deterministic; last block resets for next replay.
__device__ unsigned int g_minbits[N];         // zero-initialized
__device__ unsigned int g_count = 0;

__global__ __launch_bounds__(512)
void fused_min_dist_kernel(const float* __restrict__ inputs,
                           const float* __restrict__ samples,
                           float* __restrict__ out) {
    const int n = blockIdx.x >> 4;
    const int s = blockIdx.x & 15;

    const float4* __restrict__ in4 =
        reinterpret_cast<const float4*>(inputs + (size_t)n * CHW);
    const float4* __restrict__ sm4 =
        reinterpret_cast<const float4*>(samples + ((size_t)n * S + s) * CHW);

    // R1-proven stream shape: 24 iters/thread, 2 plain float4 loads, unroll 4.
    float acc = 0.0f;
    #pragma unroll 4
    for (int i = threadIdx.x; i < CHW4; i += 512) {
        float4 a = in4[i];
        float4 b = sm4[i];
        float dx = b.x - a.x;
        float dy = b.y - a.y;
        float dz = b.z - a.z;
        float dw = b.w - a.w;
        acc = fmaf(dx, dx, acc);
        acc = fmaf(dy, dy, acc);
        acc = fmaf(dz, dz, acc);
        acc = fmaf(dw, dw, acc);
    }

    // Block reduction: warp shuffle then cross-warp via shared.
    __shared__ float sdata[16];
    #pragma unroll
    for (int o = 16; o > 0; o >>= 1)
        acc += __shfl_down_sync(0xffffffffu, acc, o);

    const int lane = threadIdx.x & 31;
    const int wid  = threadIdx.x >> 5;
    if (lane == 0) sdata[wid] = acc;
    __syncthreads();

    __shared__ bool is_last;
    if (wid == 0) {
        acc = (lane < 16) ? sdata[lane] : 0.0f;
        #pragma unroll
        for (int o = 8; o > 0; o >>= 1)
            acc += __shfl_down_sync(0xffffffffu, acc, o);
        if (lane == 0) {
            // min(dist) via max of inverted bits (dist >= 0).
            atomicMax(&g_minbits[n], ~__float_as_uint(acc));
            __threadfence();
            unsigned int prev = atomicInc(&g_count, GRID - 1);  // self-resetting
            is_last = (prev == GRID - 1);
        }
    }
    __syncthreads();

    // ---- last block: sum the 64 per-batch minima, write scalar, reset state ----
    if (is_last) {
        __shared__ float mins[N];
        if (threadIdx.x < N) {
            unsigned int b = __ldcg(&g_minbits[threadIdx.x]);   // L1-bypass, coherent
            mins[threadIdx.x] = __uint_as_float(~b);
            g_minbits[threadIdx.x] = 0u;    // reset for next graph replay
        }
        __syncthreads();
        if (threadIdx.x == 0) {
            float total = 0.0f;
            #pragma unroll
            for (int nn = 0; nn < N; nn++)
                total += mins[nn];          // fixed order -> deterministic
            out[0] = total;
        }
    }
}

extern "C" void kernel_launch(void* const* d_in, const int* in_sizes, int n_in,
                              void* d_out, int out_size) {
    const float* inputs  = (const float*)d_in[0];   // [64,3,128,128]
    const float* samples = (const float*)d_in[1];   // [64,16,3,128,128]
    float* out = (float*)d_out;

    fused_min_dist_kernel<<<GRID, 512>>>(inputs, samples, out);
}